// round 2
// baseline (speedup 1.0000x reference)
#include <cuda_runtime.h>
#include <math.h>

// Shapes fixed by setup_inputs
#define LLL 3
#define BBB 2
#define QQQ 100
#define CCC 2
#define NGT 20
#define HM  128
#define HF  512
#define DSZ 64
#define PPX (DSZ*DSZ)        // 4096
#define LB  (LLL*BBB)        // 6
#define BN  (BBB*NGT)        // 40
#define MQ  (LLL*BBB*QQQ)    // 600
#define NPAIR (LLL*BBB*NGT)  // 120

// ---------------- static device scratch (no allocation) ----------------
__device__ float  d_w2w[DSZ][16];   // 64<-512 antialiased triangle weights
__device__ int    d_w2s[DSZ];
__device__ float  d_mw[DSZ][8];     // composite 64<-512<-128 weights
__device__ int    d_ms[DSZ];
__device__ float  d_tmp1[BN*HF*DSZ];
__device__ float  d_mds[BN*PPX];
__device__ float  d_msum[BN];
__device__ float  d_tmpq[MQ*HM*DSZ];
__device__ float  d_qds[MQ*PPX];
__device__ double d_costT[LB*NGT*QQQ];  // [inst][n][q]
__device__ int    d_qmatch[LB*NGT];     // matched query per gt
__device__ double d_part[NPAIR*64*4];   // mask-loss partials

// -----------------------------------------------------------------------
// Resize weights (jax.image.resize semantics, antialias=True).
// sample = (o+0.5)*in/out - 0.5 ; triangle kernel with scale max(in/out,1);
// per-output normalization over in-range taps (== clamp for upsample).
__global__ void k_weights() {
    int o = threadIdx.x;
    if (o >= DSZ) return;
    double s2 = (o + 0.5) * 8.0 - 0.5;           // 512 -> 64
    int start = 8 * o - 4;
    if (start < 0) start = 0;
    if (start > HF - 16) start = HF - 16;
    double w[16]; double norm = 0.0;
    for (int t = 0; t < 16; t++) {
        double d = fabs(s2 - (double)(start + t)) / 8.0;
        w[t] = (d < 1.0) ? (1.0 - d) : 0.0;
        norm += w[t];
    }
    for (int t = 0; t < 16; t++) {
        w[t] /= norm;
        d_w2w[o][t] = (float)w[t];
    }
    d_w2s[o] = start;

    // composite 64 <- 512 <- 128 (down @ up)
    int js = 2 * o - 2;
    if (js < 0) js = 0;
    if (js > HM - 8) js = HM - 8;
    d_ms[o] = js;
    double row[8] = {0,0,0,0,0,0,0,0};
    for (int t = 0; t < 16; t++) {
        if (w[t] <= 0.0) continue;
        int k = start + t;
        double s1 = (k + 0.5) * 0.25 - 0.5;       // 128 -> 512 bilinear sample
        double fj = floor(s1);
        int j0 = (int)fj;
        double f = s1 - fj;
        if (j0 < 0)       { j0 = 0;      f = 0.0; }  // renorm == clamp
        if (j0 >= HM - 1) { j0 = HM - 1; f = 0.0; }
        int a = j0 - js;
        if (a >= 0 && a < 8) row[a] += w[t] * (1.0 - f);
        if (f > 0.0) {
            int b2 = j0 + 1 - js;
            if (b2 >= 0 && b2 < 8) row[b2] += w[t] * f;
        }
    }
    for (int t = 0; t < 8; t++) d_mw[o][t] = (float)row[t];
}

// -------- gt mask downsample 512 -> 64 (separable) --------
__global__ void k_mds1(const int* __restrict__ gm) {
    int idx = blockIdx.x * blockDim.x + threadIdx.x;
    if (idx >= BN * HF * DSZ) return;
    int ox = idx & 63;
    int y  = (idx >> 6) & 511;
    int bn = idx >> 15;
    const int* row = gm + ((long)bn * HF + y) * HF + d_w2s[ox];
    float s = 0.f;
#pragma unroll
    for (int t = 0; t < 16; t++) s += d_w2w[ox][t] * (float)row[t];
    d_tmp1[idx] = s;
}

__global__ void k_mds2() {
    int idx = blockIdx.x * blockDim.x + threadIdx.x;
    if (idx >= BN * PPX) return;
    int ox = idx & 63;
    int oy = (idx >> 6) & 63;
    int bn = idx >> 12;
    int s0 = d_w2s[oy];
    const float* col = d_tmp1 + (bn * HF + s0) * DSZ + ox;
    float s = 0.f;
#pragma unroll
    for (int t = 0; t < 16; t++) s += d_w2w[oy][t] * col[t * DSZ];
    d_mds[idx] = s;
}

__global__ void k_msum() {
    int bn = blockIdx.x;
    float a = 0.f;
    for (int p = threadIdx.x; p < PPX; p += 128) a += d_mds[bn * PPX + p];
    __shared__ float sh[128];
    sh[threadIdx.x] = a; __syncthreads();
    for (int s = 64; s > 0; s >>= 1) {
        if (threadIdx.x < s) sh[threadIdx.x] += sh[threadIdx.x + s];
        __syncthreads();
    }
    if (threadIdx.x == 0) d_msum[bn] = sh[0];
}

// -------- query downsample 128 -> 64 via composite weights --------
__global__ void k_qds1(const float* __restrict__ pm) {
    int idx = blockIdx.x * blockDim.x + threadIdx.x;
    if (idx >= MQ * HM * DSZ) return;
    int ox = idx & 63;
    int y  = (idx >> 6) & 127;
    int m  = idx >> 13;
    const float* row = pm + ((long)m * HM + y) * HM + d_ms[ox];
    float s = 0.f;
#pragma unroll
    for (int t = 0; t < 8; t++) s += d_mw[ox][t] * row[t];
    d_tmpq[idx] = s;
}

__global__ void k_qds2() {
    int idx = blockIdx.x * blockDim.x + threadIdx.x;
    if (idx >= MQ * PPX) return;
    int ox = idx & 63;
    int oy = (idx >> 6) & 63;
    int m  = idx >> 12;
    int s0 = d_ms[oy];
    const float* col = d_tmpq + (m * HM + s0) * DSZ + ox;
    float s = 0.f;
#pragma unroll
    for (int t = 0; t < 8; t++) s += d_mw[oy][t] * col[t * DSZ];
    d_qds[idx] = s;
}

// -------- matcher cost: one block per (l,b,q) --------
// focal term per px is cubic in t: (pr + a t)^2 (sp - x t), a = 1-2pr
__global__ void __launch_bounds__(256) k_cost(const float* __restrict__ logits,
                                              const int* __restrict__ labels) {
    int m  = blockIdx.x;            // (l*B+b)*Q + q
    int lb = m / QQQ;
    int q  = m - lb * QQQ;
    int b  = lb % BBB;
    const float* xr = d_qds + (long)m * PPX;
    const float* tb = d_mds + (long)b * NGT * PPX;
    int tid  = threadIdx.x;
    int wid  = tid >> 5;
    int lane = tid & 31;

    float c1[16], c2[16], c3[16], prv[16];
    float c0s = 0.f, prs = 0.f;
    const float4* x4 = (const float4*)xr + tid * 4;
#pragma unroll
    for (int v = 0; v < 4; v++) {
        float4 xv = x4[v];
        float xs[4] = {xv.x, xv.y, xv.z, xv.w};
#pragma unroll
        for (int k2 = 0; k2 < 4; k2++) {
            int k = v * 4 + k2;
            float x = xs[k2];
            float e = __expf(-fabsf(x));
            float inv = __fdividef(1.f, 1.f + e);
            float pr = (x >= 0.f) ? inv : e * inv;
            float sp = fmaxf(x, 0.f) + __logf(1.f + e);
            float a  = 1.f - 2.f * pr;
            float pr2 = pr * pr;
            c0s += pr2 * sp;
            c1[k] = 2.f * pr * a * sp - pr2 * x;
            c2[k] = a * a * sp - 2.f * pr * a * x;
            c3[k] = -a * a * x;
            prv[k] = pr;
            prs += pr;
        }
    }

    __shared__ float swA[8], swB[8];
    __shared__ float s_c0, s_prob, s_p0, s_p1;
    // reduce c0s, prs
#pragma unroll
    for (int off = 16; off; off >>= 1) {
        c0s += __shfl_down_sync(0xffffffffu, c0s, off);
        prs += __shfl_down_sync(0xffffffffu, prs, off);
    }
    if (lane == 0) { swA[wid] = c0s; swB[wid] = prs; }
    __syncthreads();
    if (tid == 0) {
        float a = 0.f, p = 0.f;
        for (int w = 0; w < 8; w++) { a += swA[w]; p += swB[w]; }
        s_c0 = a; s_prob = p;
        const float* lg = logits + (long)m * CCC;
        float x0 = lg[0], x1 = lg[1];
        float mx = fmaxf(x0, x1);
        float e0 = __expf(x0 - mx), e1 = __expf(x1 - mx);
        float is = __fdividef(1.f, e0 + e1);
        s_p0 = e0 * is; s_p1 = e1 * is;
    }
    __syncthreads();

    for (int n = 0; n < NGT; n++) {
        const float4* t4 = (const float4*)(tb + (long)n * PPX) + tid * 4;
        float fa = 0.f, ia = 0.f;
#pragma unroll
        for (int v = 0; v < 4; v++) {
            float4 tv = t4[v];
            float ts[4] = {tv.x, tv.y, tv.z, tv.w};
#pragma unroll
            for (int k2 = 0; k2 < 4; k2++) {
                int k = v * 4 + k2;
                float t = ts[k2];
                fa += ((c3[k] * t + c2[k]) * t + c1[k]) * t;
                ia += prv[k] * t;
            }
        }
#pragma unroll
        for (int off = 16; off; off >>= 1) {
            fa += __shfl_down_sync(0xffffffffu, fa, off);
            ia += __shfl_down_sync(0xffffffffu, ia, off);
        }
        if (lane == 0) { swA[wid] = fa; swB[wid] = ia; }
        __syncthreads();
        if (tid == 0) {
            float fs = 0.f, is2 = 0.f;
            for (int w = 0; w < 8; w++) { fs += swA[w]; is2 += swB[w]; }
            float focal = 0.25f * (s_c0 + fs) * (1.f / (float)PPX);
            float dice  = 1.f - (2.f * is2 + 1.f) / (s_prob + d_msum[b * NGT + n] + 1.f);
            int lab = labels[b * NGT + n];
            float cc = -(lab ? s_p1 : s_p0);
            d_costT[(long)lb * (NGT * QQQ) + n * QQQ + q] = (double)(cc + focal + dice);
        }
        __syncthreads();
    }
}

// -------- Hungarian (Jonker-Volgenant, e-maxx), one warp per (l,b) --------
#define JINF 1e30
__global__ void k_jv() {
    int inst = blockIdx.x;
    int lane = threadIdx.x;
    __shared__ double Cs[NGT * QQQ];
    __shared__ double u[NGT + 1];
    __shared__ int p[QQQ + 1], way[QQQ + 1], usedS[QQQ + 1];
    const double* Cg = d_costT + (long)inst * NGT * QQQ;
    for (int k = lane; k < NGT * QQQ; k += 32) Cs[k] = Cg[k];
    for (int k = lane; k <= QQQ; k += 32) { p[k] = 0; way[k] = 0; }
    for (int k = lane; k <= NGT; k += 32) u[k] = 0.0;
    double v[4];
#pragma unroll
    for (int s = 0; s < 4; s++) v[s] = 0.0;
    __syncwarp();

    for (int i = 1; i <= NGT; i++) {
        if (lane == 0) p[0] = i;
        double minv[4];
        int used_b = 0;
#pragma unroll
        for (int s = 0; s < 4; s++) minv[s] = JINF;
        for (int k = lane; k <= QQQ; k += 32) usedS[k] = 0;
        __syncwarp();
        int j0 = 0;
        while (true) {
            // mark used[j0]
            if (j0 > 0) {
                int s = (j0 - 1) >> 5, ol = (j0 - 1) & 31;
                if (lane == ol) used_b |= (1 << s);
            }
            if (lane == 0) usedS[j0] = 1;
            __syncwarp();
            int i0 = p[j0];
            double ui0 = u[i0];
            double bv = JINF; int bj = QQQ + 1;
#pragma unroll
            for (int s = 0; s < 4; s++) {
                int j = 1 + lane + 32 * s;
                if (j <= QQQ && !((used_b >> s) & 1)) {
                    double cur = Cs[(i0 - 1) * QQQ + (j - 1)] - ui0 - v[s];
                    if (cur < minv[s]) { minv[s] = cur; way[j] = j0; }
                    if (minv[s] < bv) { bv = minv[s]; bj = j; }
                }
            }
            // argmin (value, then smallest j) across warp
#pragma unroll
            for (int off = 16; off; off >>= 1) {
                double ov = __shfl_down_sync(0xffffffffu, bv, off);
                int oj = __shfl_down_sync(0xffffffffu, bj, off);
                if (ov < bv || (ov == bv && oj < bj)) { bv = ov; bj = oj; }
            }
            bv = __shfl_sync(0xffffffffu, bv, 0);
            bj = __shfl_sync(0xffffffffu, bj, 0);
            double delta = bv; int j1 = bj;
            if (lane == 0) u[p[0]] += delta;   // j=0 always used
#pragma unroll
            for (int s = 0; s < 4; s++) {
                int j = 1 + lane + 32 * s;
                if (j <= QQQ) {
                    if ((used_b >> s) & 1) { u[p[j]] += delta; v[s] -= delta; }
                    else                    minv[s] -= delta;
                }
            }
            __syncwarp();
            j0 = j1;
            if (p[j0] == 0) break;
        }
        if (lane == 0) {
            while (j0) { int j1 = way[j0]; p[j0] = p[j1]; j0 = j1; }
        }
        __syncwarp();
    }
    for (int j = 1 + lane; j <= QQQ; j += 32)
        if (p[j] > 0) d_qmatch[inst * NGT + (p[j] - 1)] = j - 1;
}

// -------- full-res mask loss for matched pairs --------
// x4 bilinear upsample phase weights; gt binary
__global__ void __launch_bounds__(256) k_maskloss(const float* __restrict__ pm,
                                                  const int* __restrict__ gm) {
    int P   = blockIdx.x >> 6;     // pair 0..119
    int blk = blockIdx.x & 63;
    int inst = P / NGT;
    int n    = P - inst * NGT;
    int b    = inst % BBB;
    int q    = d_qmatch[P];
    const float* xm = pm + ((long)(inst * QQQ + q)) * HM * HM;
    const int*   g  = gm + ((long)(b * NGT + n)) * HF * HF;

    int tile = blk * 256 + threadIdx.x;   // 0..16383
    int tx = tile & 127, ty = tile >> 7;
    int xm1 = tx > 0 ? tx - 1 : 0;
    int xp1 = tx < 127 ? tx + 1 : 127;
    int ym1 = ty > 0 ? ty - 1 : 0;
    int yp1 = ty < 127 ? ty + 1 : 127;

    float h[3][4];
    int rows[3] = {ym1, ty, yp1};
#pragma unroll
    for (int r = 0; r < 3; r++) {
        const float* rp = xm + rows[r] * HM;
        float v0 = rp[xm1], v1 = rp[tx], v2 = rp[xp1];
        h[r][0] = 0.375f * v0 + 0.625f * v1;
        h[r][1] = 0.125f * v0 + 0.875f * v1;
        h[r][2] = 0.875f * v1 + 0.125f * v2;
        h[r][3] = 0.625f * v1 + 0.375f * v2;
    }
    const float wA[4] = {0.375f, 0.125f, 0.875f, 0.625f};
    const float wB[4] = {0.625f, 0.875f, 0.125f, 0.375f};

    float fac = 0.f, prs = 0.f, ins = 0.f, gts = 0.f;
#pragma unroll
    for (int phy = 0; phy < 4; phy++) {
        int ra = (phy < 2) ? 0 : 1;
        int rb = ra + 1;
        const int4 gr = *(const int4*)(g + (4 * ty + phy) * HF + 4 * tx);
        int gv[4] = {gr.x, gr.y, gr.z, gr.w};
#pragma unroll
        for (int phx = 0; phx < 4; phx++) {
            float x = wA[phy] * h[ra][phx] + wB[phy] * h[rb][phx];
            float e = __expf(-fabsf(x));
            float inv = __fdividef(1.f, 1.f + e);
            float pr = (x >= 0.f) ? inv : e * inv;
            float sp = fmaxf(x, 0.f) + __logf(1.f + e);
            if (gv[phx]) {
                float om = 1.f - pr;
                fac += 0.25f * om * om * (sp - x);
                ins += pr;
                gts += 1.f;
            } else {
                fac += 0.75f * pr * pr * sp;
            }
            prs += pr;
        }
    }
    __shared__ float4 sh[256];
    sh[threadIdx.x] = make_float4(fac, prs, ins, gts);
    __syncthreads();
    for (int s = 128; s > 0; s >>= 1) {
        if (threadIdx.x < s) {
            float4 a = sh[threadIdx.x], c = sh[threadIdx.x + s];
            sh[threadIdx.x] = make_float4(a.x + c.x, a.y + c.y, a.z + c.z, a.w + c.w);
        }
        __syncthreads();
    }
    if (threadIdx.x == 0) {
        float4 r = sh[0];
        double* o = d_part + ((long)P * 64 + blk) * 4;
        o[0] = (double)r.x; o[1] = (double)r.y; o[2] = (double)r.z; o[3] = (double)r.w;
    }
}

// -------- final combine: CE + focal + dice, deterministic --------
__global__ void k_final(const float* __restrict__ logits,
                        const int* __restrict__ labels,
                        float* __restrict__ out) {
    int tid = threadIdx.x;  // 128
    __shared__ double shf[NPAIR], shd[NPAIR];
    if (tid < NPAIR) {
        double f = 0, pp = 0, ii = 0, gg = 0;
        for (int k = 0; k < 64; k++) {
            const double* pr = d_part + ((long)tid * 64 + k) * 4;
            f += pr[0]; pp += pr[1]; ii += pr[2]; gg += pr[3];
        }
        shf[tid] = f;
        shd[tid] = 1.0 - (2.0 * ii + 1.0) / (pp + gg + 1.0);
    }
    __shared__ int tq[BBB * QQQ];
    __shared__ double rnum[128], rden[128];
    __shared__ double layer_ce[LLL];
    __syncthreads();
    for (int l = 0; l < LLL; l++) {
        for (int k = tid; k < BBB * QQQ; k += 128) tq[k] = CCC - 1;  // no-object
        __syncthreads();
        if (tid < BBB * NGT) {
            int b = tid / NGT, n = tid - b * NGT;
            int q = d_qmatch[(l * BBB + b) * NGT + n];
            tq[b * QQQ + q] = labels[b * NGT + n];
        }
        __syncthreads();
        double num = 0, den = 0;
        for (int k = tid; k < BBB * QQQ; k += 128) {
            const float* lg = logits + ((long)l * BBB * QQQ + k) * CCC;
            double x0 = lg[0], x1 = lg[1];
            double mx = fmax(x0, x1);
            double lse = mx + log(exp(x0 - mx) + exp(x1 - mx));
            int t = tq[k];
            double lp = (t ? x1 : x0) - lse;
            double w = (t == CCC - 1) ? 0.1 : 1.0;
            num += -w * lp;
            den += w;
        }
        rnum[tid] = num; rden[tid] = den;
        __syncthreads();
        for (int s = 64; s > 0; s >>= 1) {
            if (tid < s) { rnum[tid] += rnum[tid + s]; rden[tid] += rden[tid + s]; }
            __syncthreads();
        }
        if (tid == 0) layer_ce[l] = rnum[0] / rden[0];
        __syncthreads();
    }
    if (tid == 0) {
        double total = 0.0;
        for (int l = 0; l < LLL; l++) {
            double fs = 0.0, ds = 0.0;
            for (int k = 0; k < BN; k++) { fs += shf[l * BN + k]; ds += shd[l * BN + k]; }
            total += 2.0 * layer_ce[l]
                   + 5.0 * fs / ((double)BN * (double)HF * (double)HF)
                   + 5.0 * ds / (double)BN;
        }
        out[0] = (float)total;
    }
}

extern "C" void kernel_launch(void* const* d_in, const int* in_sizes, int n_in,
                              void* d_out, int out_size) {
    (void)in_sizes; (void)n_in; (void)out_size;
    const float* logits = (const float*)d_in[0];   // (L,B,Q,C)
    const float* pm     = (const float*)d_in[1];   // (L,B,Q,128,128)
    const int*   labels = (const int*)d_in[2];     // (B,N)
    const int*   gm     = (const int*)d_in[3];     // (B,N,512,512)
    float* out = (float*)d_out;

    k_weights<<<1, 64>>>();
    k_mds1<<<(BN * HF * DSZ + 255) / 256, 256>>>(gm);
    k_mds2<<<(BN * PPX + 255) / 256, 256>>>();
    k_msum<<<BN, 128>>>();
    k_qds1<<<(MQ * HM * DSZ + 255) / 256, 256>>>(pm);
    k_qds2<<<(MQ * PPX + 255) / 256, 256>>>();
    k_cost<<<MQ, 256>>>(logits, labels);
    k_jv<<<LB, 32>>>();
    k_maskloss<<<NPAIR * 64, 256>>>(pm, gm);
    k_final<<<1, 128>>>(logits, labels, out);
}

// round 3
// speedup vs baseline: 1.2598x; 1.2598x over previous
#include <cuda_runtime.h>
#include <math.h>

// Shapes fixed by setup_inputs
#define LLL 3
#define BBB 2
#define QQQ 100
#define CCC 2
#define NGT 20
#define HM  128
#define HF  512
#define DSZ 64
#define PPX (DSZ*DSZ)        // 4096
#define LB  (LLL*BBB)        // 6
#define BN  (BBB*NGT)        // 40
#define MQ  (LLL*BBB*QQQ)    // 600
#define NPAIR (LLL*BBB*NGT)  // 120

// ---------------- static device scratch (no allocation) ----------------
__device__ float  d_w2w[DSZ][16];   // 64<-512 antialiased triangle weights
__device__ int    d_w2s[DSZ];
__device__ float  d_mw[DSZ][8];     // composite 64<-512<-128 weights
__device__ int    d_ms[DSZ];
__device__ float  d_tmp1[BN*HF*DSZ];
__device__ float  d_mds[BN*PPX];
__device__ float  d_msp[BN*16];         // per-block partial sums of mds
__device__ double d_costT[LB*NGT*QQQ];  // [inst][n][q]
__device__ int    d_qmatch[LB*NGT];     // matched query per gt
__device__ double d_part[NPAIR*64*4];   // mask-loss partials

// -----------------------------------------------------------------------
// Resize weights (jax.image.resize semantics, antialias=True).
__global__ void k_weights() {
    int o = threadIdx.x;
    if (o >= DSZ) return;
    double s2 = (o + 0.5) * 8.0 - 0.5;           // 512 -> 64
    int start = 8 * o - 4;
    if (start < 0) start = 0;
    if (start > HF - 16) start = HF - 16;
    double w[16]; double norm = 0.0;
    for (int t = 0; t < 16; t++) {
        double d = fabs(s2 - (double)(start + t)) / 8.0;
        w[t] = (d < 1.0) ? (1.0 - d) : 0.0;
        norm += w[t];
    }
    for (int t = 0; t < 16; t++) {
        w[t] /= norm;
        d_w2w[o][t] = (float)w[t];
    }
    d_w2s[o] = start;

    // composite 64 <- 512 <- 128 (down @ up)
    int js = 2 * o - 2;
    if (js < 0) js = 0;
    if (js > HM - 8) js = HM - 8;
    d_ms[o] = js;
    double row[8] = {0,0,0,0,0,0,0,0};
    for (int t = 0; t < 16; t++) {
        if (w[t] <= 0.0) continue;
        int k = start + t;
        double s1 = (k + 0.5) * 0.25 - 0.5;       // 128 -> 512 bilinear sample
        double fj = floor(s1);
        int j0 = (int)fj;
        double f = s1 - fj;
        if (j0 < 0)       { j0 = 0;      f = 0.0; }  // renorm == clamp
        if (j0 >= HM - 1) { j0 = HM - 1; f = 0.0; }
        int a = j0 - js;
        if (a >= 0 && a < 8) row[a] += w[t] * (1.0 - f);
        if (f > 0.0) {
            int b2 = j0 + 1 - js;
            if (b2 >= 0 && b2 < 8) row[b2] += w[t] * f;
        }
    }
    for (int t = 0; t < 8; t++) d_mw[o][t] = (float)row[t];
}

// -------- gt mask downsample 512 -> 64 (separable) --------
__global__ void k_mds1(const int* __restrict__ gm) {
    int idx = blockIdx.x * blockDim.x + threadIdx.x;
    if (idx >= BN * HF * DSZ) return;
    int ox = idx & 63;
    int y  = (idx >> 6) & 511;
    int bn = idx >> 15;
    const int* row = gm + ((long)bn * HF + y) * HF + d_w2s[ox];
    float s = 0.f;
#pragma unroll
    for (int t = 0; t < 16; t++) s += d_w2w[ox][t] * (float)row[t];
    d_tmp1[idx] = s;
}

// mds2 + fused per-block partial sums (16 blocks per bn, deterministic)
__global__ void k_mds2() {
    int idx = blockIdx.x * blockDim.x + threadIdx.x;
    int ox = idx & 63;
    int oy = (idx >> 6) & 63;
    int bn = idx >> 12;
    int s0 = d_w2s[oy];
    const float* col = d_tmp1 + (bn * HF + s0) * DSZ + ox;
    float s = 0.f;
#pragma unroll
    for (int t = 0; t < 16; t++) s += d_w2w[oy][t] * col[t * DSZ];
    d_mds[idx] = s;
    __shared__ float sh[256];
    sh[threadIdx.x] = s;
    __syncthreads();
    for (int st = 128; st > 0; st >>= 1) {
        if (threadIdx.x < st) sh[threadIdx.x] += sh[threadIdx.x + st];
        __syncthreads();
    }
    if (threadIdx.x == 0) d_msp[blockIdx.x] = sh[0];  // blockIdx = bn*16 + sub
}

// -------- fused query downsample + matcher cost: one block per (l,b,q) ----
// focal term per px is cubic in t: (pr + a t)^2 (sp - x t), a = 1-2pr
__global__ void __launch_bounds__(256, 2) k_cost(const float* __restrict__ pm,
                                                 const float* __restrict__ logits,
                                                 const int* __restrict__ labels) {
    __shared__ float s_pm[16][128];
    __shared__ float s_tmp[128][68];
    __shared__ float s_mw[64][8];
    __shared__ int   s_ms[64];
    __shared__ float s_fa[NGT][8], s_ia[NGT][8];
    __shared__ float s_c0[8], s_pr[8];

    int m  = blockIdx.x;            // (l*B+b)*Q + q
    int lb = m / QQQ;
    int q  = m - lb * QQQ;
    int b  = lb % BBB;
    int tid  = threadIdx.x;
    int wid  = tid >> 5;
    int lane = tid & 31;

    if (tid < 64) {
        s_ms[tid] = d_ms[tid];
#pragma unroll
        for (int t = 0; t < 8; t++) s_mw[tid][t] = d_mw[tid][t];
    }
    __syncthreads();

    // ---- stage 1: horizontal downsample pm[m] 128x128 -> tmp 128x64 ----
    const float4* pmv = (const float4*)(pm + (long)m * (HM * HM));
    for (int c = 0; c < 8; c++) {
#pragma unroll
        for (int r = 0; r < 2; r++) {
            int f = tid + 256 * r;          // 0..511
            int yl = f >> 5;                // row within chunk
            int x4 = f & 31;
            float4 vv = pmv[(c * 16 + yl) * 32 + x4];
            *(float4*)&s_pm[yl][x4 * 4] = vv;
        }
        __syncthreads();
#pragma unroll
        for (int k = 0; k < 4; k++) {
            int o  = tid + 256 * k;         // 0..1023
            int yl = o >> 6;
            int ox = o & 63;
            const float* rp = &s_pm[yl][s_ms[ox]];
            float acc = 0.f;
#pragma unroll
            for (int t = 0; t < 8; t++) acc += s_mw[ox][t] * rp[t];
            s_tmp[c * 16 + yl][ox] = acc;
        }
        __syncthreads();
    }

    // ---- stage 2: vertical downsample -> x[16] in registers ----
    // thread covers flat px [tid*16, tid*16+16): oy = tid>>2, ox0 = (tid&3)*16
    int oy  = tid >> 2;
    int ox0 = (tid & 3) * 16;
    int r0  = s_ms[oy];
    float x[16];
#pragma unroll
    for (int k = 0; k < 16; k++) x[k] = 0.f;
#pragma unroll
    for (int t = 0; t < 8; t++) {
        float wv = s_mw[oy][t];
        const float* rp = &s_tmp[r0 + t][ox0];
#pragma unroll
        for (int k = 0; k < 16; k++) x[k] += wv * rp[k];
    }

    // ---- per-pixel coefficients ----
    float c1[16], c2[16], c3[16], prv[16];
    float c0s = 0.f, prs = 0.f;
#pragma unroll
    for (int k = 0; k < 16; k++) {
        float xx = x[k];
        float e = __expf(-fabsf(xx));
        float inv = __fdividef(1.f, 1.f + e);
        float pr = (xx >= 0.f) ? inv : e * inv;
        float sp = fmaxf(xx, 0.f) + __logf(1.f + e);
        float a  = 1.f - 2.f * pr;
        float pr2 = pr * pr;
        c0s += pr2 * sp;
        c1[k] = 2.f * pr * a * sp - pr2 * xx;
        c2[k] = a * a * sp - 2.f * pr * a * xx;
        c3[k] = -a * a * xx;
        prv[k] = pr;
        prs += pr;
    }
#pragma unroll
    for (int off = 16; off; off >>= 1) {
        c0s += __shfl_down_sync(0xffffffffu, c0s, off);
        prs += __shfl_down_sync(0xffffffffu, prs, off);
    }
    if (lane == 0) { s_c0[wid] = c0s; s_pr[wid] = prs; }

    // ---- main loop over gts: per-warp partials, no block sync inside ----
    const float* tb = d_mds + (long)b * NGT * PPX;
    for (int n = 0; n < NGT; n++) {
        const float4* t4 = (const float4*)(tb + (long)n * PPX) + tid * 4;
        float fa = 0.f, ia = 0.f;
#pragma unroll
        for (int v = 0; v < 4; v++) {
            float4 tv = t4[v];
            float ts[4] = {tv.x, tv.y, tv.z, tv.w};
#pragma unroll
            for (int k2 = 0; k2 < 4; k2++) {
                int k = v * 4 + k2;
                float t = ts[k2];
                fa += ((c3[k] * t + c2[k]) * t + c1[k]) * t;
                ia += prv[k] * t;
            }
        }
#pragma unroll
        for (int off = 16; off; off >>= 1) {
            fa += __shfl_down_sync(0xffffffffu, fa, off);
            ia += __shfl_down_sync(0xffffffffu, ia, off);
        }
        if (lane == 0) { s_fa[n][wid] = fa; s_ia[n][wid] = ia; }
    }
    __syncthreads();

    // ---- finalize: thread n < 20 ----
    if (tid < NGT) {
        int n = tid;
        float fs = 0.f, is2 = 0.f, c0 = 0.f, pa = 0.f;
#pragma unroll
        for (int w = 0; w < 8; w++) {
            fs += s_fa[n][w]; is2 += s_ia[n][w];
            c0 += s_c0[w];    pa  += s_pr[w];
        }
        float msum = 0.f;
        const float* mp = d_msp + (b * NGT + n) * 16;
#pragma unroll
        for (int k = 0; k < 16; k++) msum += mp[k];
        float focal = 0.25f * (c0 + fs) * (1.f / (float)PPX);
        float dice  = 1.f - (2.f * is2 + 1.f) / (pa + msum + 1.f);
        const float* lg = logits + (long)m * CCC;
        float x0 = lg[0], x1 = lg[1];
        float mx = fmaxf(x0, x1);
        float e0 = __expf(x0 - mx), e1 = __expf(x1 - mx);
        float is = __fdividef(1.f, e0 + e1);
        int lab = labels[b * NGT + n];
        float cc = -((lab ? e1 : e0) * is);
        d_costT[(long)lb * (NGT * QQQ) + n * QQQ + q] = (double)(cc + focal + dice);
    }
}

// -------- Hungarian (Jonker-Volgenant, e-maxx), one warp per (l,b) --------
#define JINF 1e30
__device__ __forceinline__ unsigned long long d2k(double x) {
    unsigned long long u = (unsigned long long)__double_as_longlong(x);
    return (u & 0x8000000000000000ULL) ? ~u : (u | 0x8000000000000000ULL);
}
__device__ __forceinline__ double k2d(unsigned long long k) {
    unsigned long long u = (k & 0x8000000000000000ULL)
                         ? (k & 0x7FFFFFFFFFFFFFFFULL) : ~k;
    return __longlong_as_double((long long)u);
}

__global__ void k_jv() {
    int inst = blockIdx.x;
    int lane = threadIdx.x;
    __shared__ double Cs[NGT * QQQ];
    __shared__ double u[NGT + 1];
    __shared__ int p[QQQ + 1], way[QQQ + 1];
    const double* Cg = d_costT + (long)inst * NGT * QQQ;
    for (int k = lane; k < NGT * QQQ; k += 32) Cs[k] = Cg[k];
    for (int k = lane; k <= QQQ; k += 32) { p[k] = 0; way[k] = 0; }
    for (int k = lane; k <= NGT; k += 32) u[k] = 0.0;
    double v[4];
#pragma unroll
    for (int s = 0; s < 4; s++) v[s] = 0.0;
    __syncwarp();

    for (int i = 1; i <= NGT; i++) {
        if (lane == 0) p[0] = i;
        double minv[4];
        int used_b = 0;
#pragma unroll
        for (int s = 0; s < 4; s++) minv[s] = JINF;
        __syncwarp();
        int j0 = 0;
        while (true) {
            if (j0 > 0) {
                int s = (j0 - 1) >> 5, ol = (j0 - 1) & 31;
                if (lane == ol) used_b |= (1 << s);
            }
            int i0 = p[j0];
            double ui0 = u[i0];
            unsigned long long bk = ~0ULL; int bj = 0x7FFFFFFF;
#pragma unroll
            for (int s = 0; s < 4; s++) {
                int j = 1 + lane + 32 * s;
                if (j <= QQQ && !((used_b >> s) & 1)) {
                    double cur = Cs[(i0 - 1) * QQQ + (j - 1)] - ui0 - v[s];
                    if (cur < minv[s]) { minv[s] = cur; way[j] = j0; }
                    unsigned long long kk = d2k(minv[s]);
                    if (kk < bk) { bk = kk; bj = j; }
                }
            }
            // warp argmin via integer REDUX (exact; first-index tie-break)
            unsigned hi = (unsigned)(bk >> 32);
            unsigned mh = __reduce_min_sync(0xffffffffu, hi);
            unsigned lo = (hi == mh) ? (unsigned)bk : 0xffffffffu;
            unsigned ml = __reduce_min_sync(0xffffffffu, lo);
            unsigned long long mk = ((unsigned long long)mh << 32) | ml;
            unsigned jc = (bk == mk) ? (unsigned)bj : 0x7fffffffu;
            int j1 = (int)__reduce_min_sync(0xffffffffu, jc);
            double delta = k2d(mk);
            if (lane == 0) u[p[0]] += delta;   // j=0 always used
#pragma unroll
            for (int s = 0; s < 4; s++) {
                int j = 1 + lane + 32 * s;
                if (j <= QQQ) {
                    if ((used_b >> s) & 1) { u[p[j]] += delta; v[s] -= delta; }
                    else                    minv[s] -= delta;
                }
            }
            __syncwarp();
            j0 = j1;
            if (p[j0] == 0) break;
        }
        if (lane == 0) {
            while (j0) { int j1 = way[j0]; p[j0] = p[j1]; j0 = j1; }
        }
        __syncwarp();
    }
    for (int j = 1 + lane; j <= QQQ; j += 32)
        if (p[j] > 0) d_qmatch[inst * NGT + (p[j] - 1)] = j - 1;
}

// -------- full-res mask loss for matched pairs --------
__global__ void __launch_bounds__(256) k_maskloss(const float* __restrict__ pm,
                                                  const int* __restrict__ gm) {
    int P   = blockIdx.x >> 6;     // pair 0..119
    int blk = blockIdx.x & 63;
    int inst = P / NGT;
    int n    = P - inst * NGT;
    int b    = inst % BBB;
    int q    = d_qmatch[P];
    const float* xm = pm + ((long)(inst * QQQ + q)) * HM * HM;
    const int*   g  = gm + ((long)(b * NGT + n)) * HF * HF;

    int tile = blk * 256 + threadIdx.x;   // 0..16383
    int tx = tile & 127, ty = tile >> 7;
    int xm1 = tx > 0 ? tx - 1 : 0;
    int xp1 = tx < 127 ? tx + 1 : 127;
    int ym1 = ty > 0 ? ty - 1 : 0;
    int yp1 = ty < 127 ? ty + 1 : 127;

    float h[3][4];
    int rows[3] = {ym1, ty, yp1};
#pragma unroll
    for (int r = 0; r < 3; r++) {
        const float* rp = xm + rows[r] * HM;
        float v0 = rp[xm1], v1 = rp[tx], v2 = rp[xp1];
        h[r][0] = 0.375f * v0 + 0.625f * v1;
        h[r][1] = 0.125f * v0 + 0.875f * v1;
        h[r][2] = 0.875f * v1 + 0.125f * v2;
        h[r][3] = 0.625f * v1 + 0.375f * v2;
    }
    const float wA[4] = {0.375f, 0.125f, 0.875f, 0.625f};
    const float wB[4] = {0.625f, 0.875f, 0.125f, 0.375f};

    float fac = 0.f, prs = 0.f, ins = 0.f, gts = 0.f;
#pragma unroll
    for (int phy = 0; phy < 4; phy++) {
        int ra = (phy < 2) ? 0 : 1;
        int rb = ra + 1;
        const int4 gr = *(const int4*)(g + (4 * ty + phy) * HF + 4 * tx);
        int gv[4] = {gr.x, gr.y, gr.z, gr.w};
#pragma unroll
        for (int phx = 0; phx < 4; phx++) {
            float x = wA[phy] * h[ra][phx] + wB[phy] * h[rb][phx];
            float e = __expf(-fabsf(x));
            float inv = __fdividef(1.f, 1.f + e);
            float pr = (x >= 0.f) ? inv : e * inv;
            float sp = fmaxf(x, 0.f) + __logf(1.f + e);
            if (gv[phx]) {
                float om = 1.f - pr;
                fac += 0.25f * om * om * (sp - x);
                ins += pr;
                gts += 1.f;
            } else {
                fac += 0.75f * pr * pr * sp;
            }
            prs += pr;
        }
    }
    __shared__ float4 sh[256];
    sh[threadIdx.x] = make_float4(fac, prs, ins, gts);
    __syncthreads();
    for (int s = 128; s > 0; s >>= 1) {
        if (threadIdx.x < s) {
            float4 a = sh[threadIdx.x], c = sh[threadIdx.x + s];
            sh[threadIdx.x] = make_float4(a.x + c.x, a.y + c.y, a.z + c.z, a.w + c.w);
        }
        __syncthreads();
    }
    if (threadIdx.x == 0) {
        float4 r = sh[0];
        double* o = d_part + ((long)P * 64 + blk) * 4;
        o[0] = (double)r.x; o[1] = (double)r.y; o[2] = (double)r.z; o[3] = (double)r.w;
    }
}

// -------- final combine: CE + focal + dice, deterministic --------
__global__ void k_final(const float* __restrict__ logits,
                        const int* __restrict__ labels,
                        float* __restrict__ out) {
    int tid = threadIdx.x;  // 128
    __shared__ double shf[NPAIR], shd[NPAIR];
    if (tid < NPAIR) {
        double f = 0, pp = 0, ii = 0, gg = 0;
        for (int k = 0; k < 64; k++) {
            const double* pr = d_part + ((long)tid * 64 + k) * 4;
            f += pr[0]; pp += pr[1]; ii += pr[2]; gg += pr[3];
        }
        shf[tid] = f;
        shd[tid] = 1.0 - (2.0 * ii + 1.0) / (pp + gg + 1.0);
    }
    __shared__ int tq[BBB * QQQ];
    __shared__ double rnum[128], rden[128];
    __shared__ double layer_ce[LLL];
    __syncthreads();
    for (int l = 0; l < LLL; l++) {
        for (int k = tid; k < BBB * QQQ; k += 128) tq[k] = CCC - 1;  // no-object
        __syncthreads();
        if (tid < BBB * NGT) {
            int b = tid / NGT, n = tid - b * NGT;
            int q = d_qmatch[(l * BBB + b) * NGT + n];
            tq[b * QQQ + q] = labels[b * NGT + n];
        }
        __syncthreads();
        double num = 0, den = 0;
        for (int k = tid; k < BBB * QQQ; k += 128) {
            const float* lg = logits + ((long)l * BBB * QQQ + k) * CCC;
            double x0 = lg[0], x1 = lg[1];
            double mx = fmax(x0, x1);
            double lse = mx + log(exp(x0 - mx) + exp(x1 - mx));
            int t = tq[k];
            double lp = (t ? x1 : x0) - lse;
            double w = (t == CCC - 1) ? 0.1 : 1.0;
            num += -w * lp;
            den += w;
        }
        rnum[tid] = num; rden[tid] = den;
        __syncthreads();
        for (int s = 64; s > 0; s >>= 1) {
            if (tid < s) { rnum[tid] += rnum[tid + s]; rden[tid] += rden[tid + s]; }
            __syncthreads();
        }
        if (tid == 0) layer_ce[l] = rnum[0] / rden[0];
        __syncthreads();
    }
    if (tid == 0) {
        double total = 0.0;
        for (int l = 0; l < LLL; l++) {
            double fs = 0.0, ds = 0.0;
            for (int k = 0; k < BN; k++) { fs += shf[l * BN + k]; ds += shd[l * BN + k]; }
            total += 2.0 * layer_ce[l]
                   + 5.0 * fs / ((double)BN * (double)HF * (double)HF)
                   + 5.0 * ds / (double)BN;
        }
        out[0] = (float)total;
    }
}

extern "C" void kernel_launch(void* const* d_in, const int* in_sizes, int n_in,
                              void* d_out, int out_size) {
    (void)in_sizes; (void)n_in; (void)out_size;
    const float* logits = (const float*)d_in[0];   // (L,B,Q,C)
    const float* pm     = (const float*)d_in[1];   // (L,B,Q,128,128)
    const int*   labels = (const int*)d_in[2];     // (B,N)
    const int*   gm     = (const int*)d_in[3];     // (B,N,512,512)
    float* out = (float*)d_out;

    k_weights<<<1, 64>>>();
    k_mds1<<<(BN * HF * DSZ + 255) / 256, 256>>>(gm);
    k_mds2<<<BN * 16, 256>>>();
    k_cost<<<MQ, 256>>>(pm, logits, labels);
    k_jv<<<LB, 32>>>();
    k_maskloss<<<NPAIR * 64, 256>>>(pm, gm);
    k_final<<<1, 128>>>(logits, labels, out);
}